// round 15
// baseline (speedup 1.0000x reference)
#include <cuda_runtime.h>
#include <cstdint>

// Conv2d N=32, CIN=3, H=W=224, COUT=64, 3x3, s1, p1, fp32.
// Implicit GEMM via mma.sync.m16n8k16 bf16->f32, 3-pass hi/lo fp32 emulation.
// R15 = R13 + quad-exchange store epilogue: per nt, partner lanes (lane^4)
// swap one co's pixel pair via 2 shfl.xor so each thread owns 4 contiguous
// pixels of ONE co-plane -> 8x STG.128 per iter instead of 16x STG.64
// (LSU issue 124 -> 96+shfl cyc/iter). Values bit-identical to R13.

#define HWDIM 224
#define IMG (HWDIM*HWDIM)        // 50176
#define COUT 64
#define CIN 3
#define NTHREADS 128
#define FULL 0xffffffffu

__device__ __forceinline__ uint32_t cvt_bf16x2(float hi, float lo) {
    uint32_t d;
    asm("cvt.rn.bf16x2.f32 %0, %1, %2;" : "=r"(d) : "f"(hi), "f"(lo));
    return d;
}
__device__ __forceinline__ void mma_bf16(float* d, const uint32_t* a, const uint32_t* b) {
    asm volatile(
        "mma.sync.aligned.m16n8k16.row.col.f32.bf16.bf16.f32 "
        "{%0,%1,%2,%3}, {%4,%5,%6,%7}, {%8,%9}, {%0,%1,%2,%3};"
        : "+f"(d[0]), "+f"(d[1]), "+f"(d[2]), "+f"(d[3])
        : "r"(a[0]), "r"(a[1]), "r"(a[2]), "r"(a[3]), "r"(b[0]), "r"(b[1]));
}

__global__ __launch_bounds__(NTHREADS, 3)
void conv_mma(const float* __restrict__ xin, const float* __restrict__ wgt,
              const float* __restrict__ bias, float* __restrict__ out)
{
    const int tid  = threadIdx.x;
    const int warp = tid >> 5;
    const int lane = tid & 31;
    const int lg   = lane >> 2;     // pixel-pair index 0..7
    const int cc   = (lane & 3) * 2;

    // grid: 32 imgs x 7 rowgroups x 14 x-segments
    const int b   = blockIdx.x;
    const int n   = b / 98;
    const int rem = b % 98;
    const int rg  = rem / 14;
    const int xc  = rem % 14;
    const float* in_n  = xin + (size_t)n * (CIN * IMG);
    float*       out_n = out + (size_t)n * (COUT * IMG);
    const int x0    = xc * 16;
    const int ybase = rg * 32 + warp * 8;

    // ---- B (weight+bias) fragments, hi/lo, built once per thread ----
    uint32_t BH[8][2][2], BL[8][2][2];
#pragma unroll
    for (int nt = 0; nt < 8; ++nt) {
        const int co = nt * 8 + lg;
#pragma unroll
        for (int s = 0; s < 2; ++s)
#pragma unroll
        for (int r = 0; r < 2; ++r) {
            const int k0 = 16 * s + cc + 8 * r;
            const int k1 = k0 + 1;
            const float f0 = (k0 < 27) ? wgt[co * 27 + k0] : (k0 == 27 ? bias[co] : 0.f);
            const float f1 = (k1 < 27) ? wgt[co * 27 + k1] : (k1 == 27 ? bias[co] : 0.f);
            const uint32_t h = cvt_bf16x2(f1, f0);
            const float l0 = f0 - __uint_as_float(h << 16);
            const float l1 = f1 - __uint_as_float(h & 0xffff0000u);
            BH[nt][s][r] = h;
            BL[nt][s][r] = cvt_bf16x2(l1, l0);
        }
    }

    // ---- patch loading setup: lane u holds x = x0 - 1 + u (u = 0..17) ----
    const bool lane_ok = (lane < 18)
                      && !(xc == 0  && lane == 0)     // x = -1
                      && !(xc == 13 && lane == 17);   // x = 224
    const float* rp = in_n + x0 - 1 + lane;           // + ci*IMG + yy*HWDIM

    // ---- prologue: patch rows for iteration 0 ----
    float P[3][3];   // P[ci][j] = row (ybase - 1 + j)
#pragma unroll
    for (int j = 0; j < 3; ++j) {
        const int yy  = ybase - 1 + j;
        const bool ok = lane_ok && ((unsigned)yy < (unsigned)HWDIM);
#pragma unroll
        for (int ci = 0; ci < CIN; ++ci)
            P[ci][j] = ok ? __ldg(rp + ci * IMG + yy * HWDIM) : 0.f;
    }

    // store-epilogue constants (quad-exchange)
    const bool oddlg   = (lg & 1);
    const int  st_co_d = oddlg ? (cc + 1) : cc;           // + nt*8
    const int  st_xb   = oddlg ? (2 * lg - 2) : (2 * lg); // 4-aligned

    for (int it = 0; it < 8; ++it) {
        const int y = ybase + it;

        // ---- distribute patch -> taps: 3 variable-src shuffles per (ci,ky) ----
        float v0[8], v1[8];
#pragma unroll
        for (int t = 0; t < 8; ++t) {
            const float d = (t == 7 && cc == 2) ? 1.f : 0.f;  // k=27 bias tap
            v0[t] = d; v1[t] = d;
        }
#pragma unroll
        for (int ci = 0; ci < CIN; ++ci)
#pragma unroll
        for (int ky = 0; ky < 3; ++ky) {
            const int k0 = ci * 9 + ky * 3;
            const int KA0  = (k0 % 2 == 0) ? k0 : k0 + 1;  // A owns KA0, KA0+1
            const int KB   = (k0 % 2 == 0) ? k0 + 2 : k0;  // B owns KB
            const int kxA0 = KA0 - k0;
            const int kxB  = KB - k0;
            const int ckA  = KA0 & 6;
            const int ckB  = KB & 6;
            const int tA0  = 2 * (KA0 >> 3) + (KA0 & 1);
            const int tA1  = 2 * ((KA0 + 1) >> 3) + ((KA0 + 1) & 1);
            const int tB   = 2 * (KB >> 3) + (KB & 1);

            const bool isA = (cc == ckA);
            const bool isB = (cc == ckB);
            const int  src = 2 * lg + (isA ? kxA0 : kxB);
            const float s0 = __shfl_sync(FULL, P[ci][ky], src);
            const float s1 = __shfl_sync(FULL, P[ci][ky], src + 1);
            const float s2 = __shfl_sync(FULL, P[ci][ky], src + 2);
            if (isA) { v0[tA0] = s0; v1[tA0] = s1; v0[tA1] = s1; v1[tA1] = s2; }
            if (isB) { v0[tB]  = s0; v1[tB]  = s1; }
        }

        // ---- split hi/lo, pack A fragments ----
        uint32_t AH[2][4], AL[2][4];
#pragma unroll
        for (int s = 0; s < 2; ++s)
#pragma unroll
        for (int r = 0; r < 2; ++r) {
            const int t0 = 4 * s + 2 * r;
            const float f00 = v0[t0], f01 = v0[t0 + 1];
            const float f10 = v1[t0], f11 = v1[t0 + 1];
            const uint32_t h0 = cvt_bf16x2(f01, f00);
            const uint32_t h1 = cvt_bf16x2(f11, f10);
            AH[s][2 * r]     = h0;
            AH[s][2 * r + 1] = h1;
            const float l00 = f00 - __uint_as_float(h0 << 16);
            const float l01 = f01 - __uint_as_float(h0 & 0xffff0000u);
            const float l10 = f10 - __uint_as_float(h1 << 16);
            const float l11 = f11 - __uint_as_float(h1 & 0xffff0000u);
            AL[s][2 * r]     = cvt_bf16x2(l01, l00);
            AL[s][2 * r + 1] = cvt_bf16x2(l11, l10);
        }

        // ---- prefetch next patch row (y+2), overlaps with MMAs ----
        float T[3];
        {
            const int yy  = y + 2;
            const bool ok = lane_ok && ((unsigned)yy < (unsigned)HWDIM);
#pragma unroll
            for (int ci = 0; ci < CIN; ++ci)
                T[ci] = ok ? __ldg(rp + ci * IMG + yy * HWDIM) : 0.f;
        }

        // ---- 48 MMAs ----
        float acc[8][4];
#pragma unroll
        for (int nt = 0; nt < 8; ++nt) {
            acc[nt][0] = 0.f; acc[nt][1] = 0.f; acc[nt][2] = 0.f; acc[nt][3] = 0.f;
        }
#pragma unroll
        for (int nt = 0; nt < 8; ++nt) {
#pragma unroll
            for (int s = 0; s < 2; ++s) {
                mma_bf16(acc[nt], AH[s], BH[nt][s]);
                mma_bf16(acc[nt], AH[s], BL[nt][s]);
                mma_bf16(acc[nt], AL[s], BH[nt][s]);
            }
        }

        // ---- store: quad-exchange -> one STG.128 per thread per nt ----
        // acc: c0=(p0,co c) c1=(p0,co c+1) c2=(p1,co c) c3=(p1,co c+1), p0=2lg.
        // Even lg keeps co c (gains partner's px 2lg+2,2lg+3);
        // odd lg keeps co c+1 (gains partner's px 2lg-2,2lg-1).
        const int pbase = y * HWDIM + x0;
#pragma unroll
        for (int nt = 0; nt < 8; ++nt) {
            const float s0 = oddlg ? acc[nt][0] : acc[nt][1];
            const float s1 = oddlg ? acc[nt][2] : acc[nt][3];
            const float r0 = __shfl_xor_sync(FULL, s0, 4);
            const float r1 = __shfl_xor_sync(FULL, s1, 4);
            float4 o;
            if (!oddlg) o = make_float4(acc[nt][0], acc[nt][2], r0, r1);
            else        o = make_float4(r0, r1, acc[nt][1], acc[nt][3]);
            const int co = nt * 8 + st_co_d;
            *reinterpret_cast<float4*>(out_n + (size_t)co * IMG + pbase + st_xb) = o;
        }

        // ---- rotate patch rows ----
#pragma unroll
        for (int ci = 0; ci < CIN; ++ci) {
            P[ci][0] = P[ci][1];
            P[ci][1] = P[ci][2];
            P[ci][2] = T[ci];
        }
    }
}

extern "C" void kernel_launch(void* const* d_in, const int* in_sizes, int n_in,
                              void* d_out, int out_size)
{
    const float* x = (const float*)d_in[0];
    const float* w = (const float*)d_in[1];
    const float* b = (const float*)d_in[2];
    float* out = (float*)d_out;

    dim3 block(NTHREADS, 1, 1);
    dim3 grid(32 * 7 * 14, 1, 1);   // 3136 blocks
    conv_mma<<<grid, block>>>(x, w, b, out);
}

// round 16
// speedup vs baseline: 1.3388x; 1.3388x over previous
#include <cuda_runtime.h>
#include <cuda_bf16.h>
#include <cstdint>

// Conv2d N=32, CIN=3, H=W=224, COUT=64, 3x3, s1, p1, fp32.
// Implicit GEMM via mma.sync.m16n8k16 bf16->f32, 3-pass hi/lo fp32 emulation.
// R16 = R13 with the input patch pre-split into packed bf16 (hi,lo) at load
// time; shuffles move the packed word and A fragments are assembled with one
// PRMT each (16 PRMTs replace ~48 cvt/shift/sub). Bit-identical to R13.

#define HWDIM 224
#define IMG (HWDIM*HWDIM)        // 50176
#define COUT 64
#define CIN 3
#define NTHREADS 128
#define FULL 0xffffffffu

__device__ __forceinline__ uint32_t cvt_bf16x2(float hi, float lo) {
    uint32_t d;
    asm("cvt.rn.bf16x2.f32 %0, %1, %2;" : "=r"(d) : "f"(hi), "f"(lo));
    return d;
}
// pack f -> [hi bf16 | lo bf16] (bytes: [l0 l1 h0 h1])
__device__ __forceinline__ uint32_t pk_split(float f) {
    const uint32_t hpair = cvt_bf16x2(f, f);                 // [_, _, h0, h1]
    const float    hf    = __uint_as_float(hpair & 0xffff0000u);
    const uint32_t lpair = cvt_bf16x2(0.f, f - hf);          // [l0, l1, _, _]
    return __byte_perm(hpair, lpair, 0x3254);                // [l0 l1 h0 h1]
}
__device__ __forceinline__ void mma_bf16(float* d, const uint32_t* a, const uint32_t* b) {
    asm volatile(
        "mma.sync.aligned.m16n8k16.row.col.f32.bf16.bf16.f32 "
        "{%0,%1,%2,%3}, {%4,%5,%6,%7}, {%8,%9}, {%0,%1,%2,%3};"
        : "+f"(d[0]), "+f"(d[1]), "+f"(d[2]), "+f"(d[3])
        : "r"(a[0]), "r"(a[1]), "r"(a[2]), "r"(a[3]), "r"(b[0]), "r"(b[1]));
}

__global__ __launch_bounds__(NTHREADS, 3)
void conv_mma(const float* __restrict__ xin, const float* __restrict__ wgt,
              const float* __restrict__ bias, float* __restrict__ out)
{
    const int tid  = threadIdx.x;
    const int warp = tid >> 5;
    const int lane = tid & 31;
    const int lg   = lane >> 2;     // pixel-pair index 0..7
    const int cc   = (lane & 3) * 2;

    // grid: 32 imgs x 7 rowgroups x 14 x-segments
    const int b   = blockIdx.x;
    const int n   = b / 98;
    const int rem = b % 98;
    const int rg  = rem / 14;
    const int xc  = rem % 14;
    const float* in_n  = xin + (size_t)n * (CIN * IMG);
    float*       out_n = out + (size_t)n * (COUT * IMG);
    const int x0    = xc * 16;
    const int ybase = rg * 32 + warp * 8;

    // ---- B (weight+bias) fragments, hi/lo, built once per thread ----
    uint32_t BH[8][2][2], BL[8][2][2];
#pragma unroll
    for (int nt = 0; nt < 8; ++nt) {
        const int co = nt * 8 + lg;
#pragma unroll
        for (int s = 0; s < 2; ++s)
#pragma unroll
        for (int r = 0; r < 2; ++r) {
            const int k0 = 16 * s + cc + 8 * r;
            const int k1 = k0 + 1;
            const float f0 = (k0 < 27) ? wgt[co * 27 + k0] : (k0 == 27 ? bias[co] : 0.f);
            const float f1 = (k1 < 27) ? wgt[co * 27 + k1] : (k1 == 27 ? bias[co] : 0.f);
            const uint32_t h = cvt_bf16x2(f1, f0);
            const float l0 = f0 - __uint_as_float(h << 16);
            const float l1 = f1 - __uint_as_float(h & 0xffff0000u);
            BH[nt][s][r] = h;
            BL[nt][s][r] = cvt_bf16x2(l1, l0);
        }
    }

    // ---- patch loading setup: lane u holds x = x0 - 1 + u (u = 0..17) ----
    const bool lane_ok = (lane < 18)
                      && !(xc == 0  && lane == 0)     // x = -1
                      && !(xc == 13 && lane == 17);   // x = 224
    const float* rp = in_n + x0 - 1 + lane;           // + ci*IMG + yy*HWDIM

    // ---- prologue: packed patch rows for iteration 0 ----
    uint32_t P[3][3];   // P[ci][j] = packed (hi,lo) of row (ybase - 1 + j)
#pragma unroll
    for (int j = 0; j < 3; ++j) {
        const int yy  = ybase - 1 + j;
        const bool ok = lane_ok && ((unsigned)yy < (unsigned)HWDIM);
#pragma unroll
        for (int ci = 0; ci < CIN; ++ci)
            P[ci][j] = ok ? pk_split(__ldg(rp + ci * IMG + yy * HWDIM)) : 0u;
    }

    for (int it = 0; it < 8; ++it) {
        const int y = ybase + it;

        // ---- distribute packed patch -> taps: 3 shuffles per (ci,ky) ----
        uint32_t v0[8], v1[8];
#pragma unroll
        for (int t = 0; t < 8; ++t) {
            // k=27 bias tap: packed(hi=bf16(1.0), lo=0) = 0x3F800000
            const uint32_t d = (t == 7 && cc == 2) ? 0x3F800000u : 0u;
            v0[t] = d; v1[t] = d;
        }
#pragma unroll
        for (int ci = 0; ci < CIN; ++ci)
#pragma unroll
        for (int ky = 0; ky < 3; ++ky) {
            const int k0 = ci * 9 + ky * 3;
            const int KA0  = (k0 % 2 == 0) ? k0 : k0 + 1;  // A owns KA0, KA0+1
            const int KB   = (k0 % 2 == 0) ? k0 + 2 : k0;  // B owns KB
            const int kxA0 = KA0 - k0;
            const int kxB  = KB - k0;
            const int ckA  = KA0 & 6;
            const int ckB  = KB & 6;
            const int tA0  = 2 * (KA0 >> 3) + (KA0 & 1);
            const int tA1  = 2 * ((KA0 + 1) >> 3) + ((KA0 + 1) & 1);
            const int tB   = 2 * (KB >> 3) + (KB & 1);

            const bool isA = (cc == ckA);
            const bool isB = (cc == ckB);
            const int  src = 2 * lg + (isA ? kxA0 : kxB);
            const uint32_t s0 = __shfl_sync(FULL, P[ci][ky], src);
            const uint32_t s1 = __shfl_sync(FULL, P[ci][ky], src + 1);
            const uint32_t s2 = __shfl_sync(FULL, P[ci][ky], src + 2);
            if (isA) { v0[tA0] = s0; v1[tA0] = s1; v0[tA1] = s1; v1[tA1] = s2; }
            if (isB) { v0[tB]  = s0; v1[tB]  = s1; }
        }

        // ---- assemble A fragments: one PRMT each ----
        uint32_t AH[2][4], AL[2][4];
#pragma unroll
        for (int s = 0; s < 2; ++s)
#pragma unroll
        for (int r = 0; r < 2; ++r) {
            const int t0 = 4 * s + 2 * r;
            AH[s][2 * r]     = __byte_perm(v0[t0], v0[t0 + 1], 0x7632);
            AH[s][2 * r + 1] = __byte_perm(v1[t0], v1[t0 + 1], 0x7632);
            AL[s][2 * r]     = __byte_perm(v0[t0], v0[t0 + 1], 0x5410);
            AL[s][2 * r + 1] = __byte_perm(v1[t0], v1[t0 + 1], 0x5410);
        }

        // ---- prefetch + split next patch row (y+2), overlaps with MMAs ----
        uint32_t T[3];
        {
            const int yy  = y + 2;
            const bool ok = lane_ok && ((unsigned)yy < (unsigned)HWDIM);
#pragma unroll
            for (int ci = 0; ci < CIN; ++ci)
                T[ci] = ok ? pk_split(__ldg(rp + ci * IMG + yy * HWDIM)) : 0u;
        }

        // ---- 48 MMAs ----
        float acc[8][4];
#pragma unroll
        for (int nt = 0; nt < 8; ++nt) {
            acc[nt][0] = 0.f; acc[nt][1] = 0.f; acc[nt][2] = 0.f; acc[nt][3] = 0.f;
        }
#pragma unroll
        for (int nt = 0; nt < 8; ++nt) {
#pragma unroll
            for (int s = 0; s < 2; ++s) {
                mma_bf16(acc[nt], AH[s], BH[nt][s]);
                mma_bf16(acc[nt], AH[s], BL[nt][s]);
                mma_bf16(acc[nt], AL[s], BH[nt][s]);
            }
        }

        // ---- store: per co, float2 of adjacent pixels (p0, p0+1) ----
        const int p0 = y * HWDIM + x0 + 2 * lg;   // even -> 8B aligned
#pragma unroll
        for (int nt = 0; nt < 8; ++nt) {
            const int co = nt * 8 + cc;
            float* pl0 = out_n + (size_t)co * IMG + p0;
            float* pl1 = pl0 + IMG;
            *reinterpret_cast<float2*>(pl0) = make_float2(acc[nt][0], acc[nt][2]);
            *reinterpret_cast<float2*>(pl1) = make_float2(acc[nt][1], acc[nt][3]);
        }

        // ---- rotate packed patch rows ----
#pragma unroll
        for (int ci = 0; ci < CIN; ++ci) {
            P[ci][0] = P[ci][1];
            P[ci][1] = P[ci][2];
            P[ci][2] = T[ci];
        }
    }
}

extern "C" void kernel_launch(void* const* d_in, const int* in_sizes, int n_in,
                              void* d_out, int out_size)
{
    const float* x = (const float*)d_in[0];
    const float* w = (const float*)d_in[1];
    const float* b = (const float*)d_in[2];
    float* out = (float*)d_out;

    dim3 block(NTHREADS, 1, 1);
    dim3 grid(32 * 7 * 14, 1, 1);   // 3136 blocks
    conv_mma<<<grid, block>>>(x, w, b, out);
}

// round 17
// speedup vs baseline: 1.5274x; 1.1409x over previous
#include <cuda_runtime.h>
#include <cstdint>

// Conv2d N=32, CIN=3, H=W=224, COUT=64, 3x3, s1, p1, fp32.
// Implicit GEMM via mma.sync.m16n8k16 bf16->f32, 3-pass hi/lo fp32 emulation.
// R17 = R13 (best: 90.3us) with pure scheduling changes:
//  (a) next-row prefetch hoisted to the TOP of each iteration (load->use
//      distance ~1 full iteration > DRAM latency),
//  (b) stores fused into the per-nt MMA loop (LSU overlaps MMA chains),
//  (c) iteration loop fully unrolled for cross-iteration pipelining.
// Instruction mix and arithmetic are identical to R13 (bit-identical output).

#define HWDIM 224
#define IMG (HWDIM*HWDIM)        // 50176
#define COUT 64
#define CIN 3
#define NTHREADS 128
#define FULL 0xffffffffu

__device__ __forceinline__ uint32_t cvt_bf16x2(float hi, float lo) {
    uint32_t d;
    asm("cvt.rn.bf16x2.f32 %0, %1, %2;" : "=r"(d) : "f"(hi), "f"(lo));
    return d;
}
__device__ __forceinline__ void mma_bf16(float* d, const uint32_t* a, const uint32_t* b) {
    asm volatile(
        "mma.sync.aligned.m16n8k16.row.col.f32.bf16.bf16.f32 "
        "{%0,%1,%2,%3}, {%4,%5,%6,%7}, {%8,%9}, {%0,%1,%2,%3};"
        : "+f"(d[0]), "+f"(d[1]), "+f"(d[2]), "+f"(d[3])
        : "r"(a[0]), "r"(a[1]), "r"(a[2]), "r"(a[3]), "r"(b[0]), "r"(b[1]));
}

__global__ __launch_bounds__(NTHREADS, 3)
void conv_mma(const float* __restrict__ xin, const float* __restrict__ wgt,
              const float* __restrict__ bias, float* __restrict__ out)
{
    const int tid  = threadIdx.x;
    const int warp = tid >> 5;
    const int lane = tid & 31;
    const int lg   = lane >> 2;     // pixel-pair index 0..7
    const int cc   = (lane & 3) * 2;

    // grid: 32 imgs x 7 rowgroups x 14 x-segments
    const int b   = blockIdx.x;
    const int n   = b / 98;
    const int rem = b % 98;
    const int rg  = rem / 14;
    const int xc  = rem % 14;
    const float* in_n  = xin + (size_t)n * (CIN * IMG);
    float*       out_n = out + (size_t)n * (COUT * IMG);
    const int x0    = xc * 16;
    const int ybase = rg * 32 + warp * 8;

    // ---- B (weight+bias) fragments, hi/lo, built once per thread ----
    uint32_t BH[8][2][2], BL[8][2][2];
#pragma unroll
    for (int nt = 0; nt < 8; ++nt) {
        const int co = nt * 8 + lg;
#pragma unroll
        for (int s = 0; s < 2; ++s)
#pragma unroll
        for (int r = 0; r < 2; ++r) {
            const int k0 = 16 * s + cc + 8 * r;
            const int k1 = k0 + 1;
            const float f0 = (k0 < 27) ? wgt[co * 27 + k0] : (k0 == 27 ? bias[co] : 0.f);
            const float f1 = (k1 < 27) ? wgt[co * 27 + k1] : (k1 == 27 ? bias[co] : 0.f);
            const uint32_t h = cvt_bf16x2(f1, f0);
            const float l0 = f0 - __uint_as_float(h << 16);
            const float l1 = f1 - __uint_as_float(h & 0xffff0000u);
            BH[nt][s][r] = h;
            BL[nt][s][r] = cvt_bf16x2(l1, l0);
        }
    }

    // ---- patch loading setup: lane u holds x = x0 - 1 + u (u = 0..17) ----
    const bool lane_ok = (lane < 18)
                      && !(xc == 0  && lane == 0)     // x = -1
                      && !(xc == 13 && lane == 17);   // x = 224
    const float* rp = in_n + x0 - 1 + lane;           // + ci*IMG + yy*HWDIM

    // ---- prologue: patch rows for iteration 0 ----
    float P[3][3];   // P[ci][j] = row (ybase - 1 + j)
#pragma unroll
    for (int j = 0; j < 3; ++j) {
        const int yy  = ybase - 1 + j;
        const bool ok = lane_ok && ((unsigned)yy < (unsigned)HWDIM);
#pragma unroll
        for (int ci = 0; ci < CIN; ++ci)
            P[ci][j] = ok ? __ldg(rp + ci * IMG + yy * HWDIM) : 0.f;
    }

#pragma unroll
    for (int it = 0; it < 8; ++it) {
        const int y = ybase + it;

        // ---- (a) prefetch next patch row (y+2) FIRST: max load->use distance ----
        float T[3];
        if (it + 1 < 8) {
            const int yy  = y + 2;
            const bool ok = lane_ok && ((unsigned)yy < (unsigned)HWDIM);
#pragma unroll
            for (int ci = 0; ci < CIN; ++ci)
                T[ci] = ok ? __ldg(rp + ci * IMG + yy * HWDIM) : 0.f;
        }

        // ---- distribute patch -> taps: 3 variable-src shuffles per (ci,ky) ----
        float v0[8], v1[8];
#pragma unroll
        for (int t = 0; t < 8; ++t) {
            const float d = (t == 7 && cc == 2) ? 1.f : 0.f;  // k=27 bias tap
            v0[t] = d; v1[t] = d;
        }
#pragma unroll
        for (int ci = 0; ci < CIN; ++ci)
#pragma unroll
        for (int ky = 0; ky < 3; ++ky) {
            const int k0 = ci * 9 + ky * 3;
            const int KA0  = (k0 % 2 == 0) ? k0 : k0 + 1;  // A owns KA0, KA0+1
            const int KB   = (k0 % 2 == 0) ? k0 + 2 : k0;  // B owns KB
            const int kxA0 = KA0 - k0;
            const int kxB  = KB - k0;
            const int ckA  = KA0 & 6;
            const int ckB  = KB & 6;
            const int tA0  = 2 * (KA0 >> 3) + (KA0 & 1);
            const int tA1  = 2 * ((KA0 + 1) >> 3) + ((KA0 + 1) & 1);
            const int tB   = 2 * (KB >> 3) + (KB & 1);

            const bool isA = (cc == ckA);
            const bool isB = (cc == ckB);
            const int  src = 2 * lg + (isA ? kxA0 : kxB);
            const float s0 = __shfl_sync(FULL, P[ci][ky], src);
            const float s1 = __shfl_sync(FULL, P[ci][ky], src + 1);
            const float s2 = __shfl_sync(FULL, P[ci][ky], src + 2);
            if (isA) { v0[tA0] = s0; v1[tA0] = s1; v0[tA1] = s1; v1[tA1] = s2; }
            if (isB) { v0[tB]  = s0; v1[tB]  = s1; }
        }

        // ---- split hi/lo, pack A fragments ----
        uint32_t AH[2][4], AL[2][4];
#pragma unroll
        for (int s = 0; s < 2; ++s)
#pragma unroll
        for (int r = 0; r < 2; ++r) {
            const int t0 = 4 * s + 2 * r;
            const float f00 = v0[t0], f01 = v0[t0 + 1];
            const float f10 = v1[t0], f11 = v1[t0 + 1];
            const uint32_t h0 = cvt_bf16x2(f01, f00);
            const uint32_t h1 = cvt_bf16x2(f11, f10);
            AH[s][2 * r]     = h0;
            AH[s][2 * r + 1] = h1;
            const float l00 = f00 - __uint_as_float(h0 << 16);
            const float l01 = f01 - __uint_as_float(h0 & 0xffff0000u);
            const float l10 = f10 - __uint_as_float(h1 << 16);
            const float l11 = f11 - __uint_as_float(h1 & 0xffff0000u);
            AL[s][2 * r]     = cvt_bf16x2(l01, l00);
            AL[s][2 * r + 1] = cvt_bf16x2(l11, l10);
        }

        // ---- (b) MMAs with fused stores: store each nt as it completes ----
        const int p0 = y * HWDIM + x0 + 2 * lg;   // even -> 8B aligned
#pragma unroll
        for (int nt = 0; nt < 8; ++nt) {
            float acc[4];
            acc[0] = 0.f; acc[1] = 0.f; acc[2] = 0.f; acc[3] = 0.f;
#pragma unroll
            for (int s = 0; s < 2; ++s) {
                mma_bf16(acc, AH[s], BH[nt][s]);
                mma_bf16(acc, AH[s], BL[nt][s]);
                mma_bf16(acc, AL[s], BH[nt][s]);
            }
            const int co = nt * 8 + cc;
            float* pl0 = out_n + (size_t)co * IMG + p0;
            float* pl1 = pl0 + IMG;
            *reinterpret_cast<float2*>(pl0) = make_float2(acc[0], acc[2]);
            *reinterpret_cast<float2*>(pl1) = make_float2(acc[1], acc[3]);
        }

        // ---- rotate patch rows ----
        if (it + 1 < 8) {
#pragma unroll
            for (int ci = 0; ci < CIN; ++ci) {
                P[ci][0] = P[ci][1];
                P[ci][1] = P[ci][2];
                P[ci][2] = T[ci];
            }
        }
    }
}

extern "C" void kernel_launch(void* const* d_in, const int* in_sizes, int n_in,
                              void* d_out, int out_size)
{
    const float* x = (const float*)d_in[0];
    const float* w = (const float*)d_in[1];
    const float* b = (const float*)d_in[2];
    float* out = (float*)d_out;

    dim3 block(NTHREADS, 1, 1);
    dim3 grid(32 * 7 * 14, 1, 1);   // 3136 blocks
    conv_mma<<<grid, block>>>(x, w, b, out);
}